// round 1
// baseline (speedup 1.0000x reference)
#include <cuda_runtime.h>

#define NPART 32
#define NPAIR 496   // 32*31/2 unordered pairs
#define HID   64
#define TPB   128
#define GRID  592

__device__ __forceinline__ float fast_tanh(float x) {
    float ax = fabsf(x);
    float e  = __expf(ax + ax);               // MUFU.EX2-based, rel err ~1e-7
    float t  = 1.0f - __fdividef(2.0f, e + 1.0f);  // e=inf -> t=1 (no NaN)
    return copysignf(t, x);
}

struct SmemLayout {
    float W1[3 * 64];     // [c][k]
    float b1[64];
    float W2[64 * 64];    // row-major [i][j]  (backward: row i contiguous over j)
    float W2T[64 * 64];   // [j][i]            (forward: row j contiguous over i)
    float b2[64];
    float W3[64];
    float pos[NPART * 3];
    float F[NPART * 3];
    float Vsum;
    unsigned char pi[NPAIR];
    unsigned char pj[NPAIR];
};

__global__ void __launch_bounds__(TPB)
discovery_kernel(const float* __restrict__ gpos,
                 const float* __restrict__ gW1, const float* __restrict__ gb1,
                 const float* __restrict__ gW2, const float* __restrict__ gb2,
                 const float* __restrict__ gW3, const float* __restrict__ gb3,
                 float* __restrict__ out, int B)
{
    __shared__ SmemLayout s;
    const int tid = threadIdx.x;

    // ---- one-time per block: weights into smem ----
    for (int k = tid; k < 192; k += TPB) s.W1[k] = gW1[k];
    for (int k = tid; k < 64; k += TPB) {
        s.b1[k] = gb1[k];
        s.b2[k] = gb2[k];
        s.W3[k] = gW3[k];
    }
    for (int k = tid; k < 4096; k += TPB) {
        float w = gW2[k];
        s.W2[k] = w;
        s.W2T[(k & 63) * 64 + (k >> 6)] = w;
    }
    const float b3v = gb3[0];

    // pair table in diagonal order: d=1..31, (i, i+d) — consecutive pairs have
    // distinct i AND distinct j, so warp-lane smem atomics hit spread addresses.
    for (int k = tid; k < NPAIR; k += TPB) {
        int d = 1, c = 0;
        while (k >= c + (NPART - d)) { c += NPART - d; d++; }
        int i = k - c;
        s.pi[k] = (unsigned char)i;
        s.pj[k] = (unsigned char)(i + d);
    }
    __syncthreads();

    for (int b = blockIdx.x; b < B; b += gridDim.x) {
        for (int k = tid; k < NPART * 3; k += TPB) {
            s.pos[k] = gpos[b * (NPART * 3) + k];
            s.F[k]   = 0.0f;
        }
        if (tid == 0) s.Vsum = 0.0f;
        __syncthreads();

        float vloc = 0.0f;

        for (int k = tid; k < NPAIR; k += TPB) {
            const int i = s.pi[k], j = s.pj[k];
            const float rx = s.pos[i * 3 + 0] - s.pos[j * 3 + 0];
            const float ry = s.pos[i * 3 + 1] - s.pos[j * 3 + 1];
            const float rz = s.pos[i * 3 + 2] - s.pos[j * 3 + 2];
            const float r2   = rx * rx + ry * ry + rz * rz;
            const float dist = sqrtf(r2);
            const float d    = fmaxf(dist, 0.05f);
            const float inv  = __fdividef(1.0f, d);
            const float inv2 = inv * inv;

            // layer 1: feats = [d, 1/d, 1/d^2]
            float h1[HID];
            #pragma unroll
            for (int kk = 0; kk < HID; kk++) {
                float z = s.b1[kk] + d * s.W1[kk] + inv * s.W1[64 + kk]
                                   + inv2 * s.W1[128 + kk];
                h1[kk] = fast_tanh(z);
            }

            // layer 2 + output head fused; also produce dz2 = W3*(1-t^2)
            float v = b3v;
            float dz2[HID];
            #pragma unroll
            for (int jj = 0; jj < HID; jj++) {
                const float4* wr = (const float4*)(&s.W2T[jj * 64]);
                float a0 = 0.f, a1 = 0.f, a2 = 0.f, a3 = 0.f;
                #pragma unroll
                for (int q = 0; q < 16; q++) {
                    float4 w = wr[q];
                    a0 = fmaf(h1[4 * q + 0], w.x, a0);
                    a1 = fmaf(h1[4 * q + 1], w.y, a1);
                    a2 = fmaf(h1[4 * q + 2], w.z, a2);
                    a3 = fmaf(h1[4 * q + 3], w.w, a3);
                }
                float z  = s.b2[jj] + ((a0 + a1) + (a2 + a3));
                float t  = fast_tanh(z);
                float w3 = s.W3[jj];
                v = fmaf(t, w3, v);
                dz2[jj] = w3 * (1.0f - t * t);
            }
            vloc += v;

            // backward: gh1 = W2 @ dz2 ; dz1 = gh1*(1-h1^2) ; gf = W1 @ dz1
            float g0 = 0.f, g1 = 0.f, g2 = 0.f;
            #pragma unroll
            for (int ii = 0; ii < HID; ii++) {
                const float4* wr = (const float4*)(&s.W2[ii * 64]);
                float a0 = 0.f, a1 = 0.f, a2 = 0.f, a3 = 0.f;
                #pragma unroll
                for (int q = 0; q < 16; q++) {
                    float4 w = wr[q];
                    a0 = fmaf(w.x, dz2[4 * q + 0], a0);
                    a1 = fmaf(w.y, dz2[4 * q + 1], a1);
                    a2 = fmaf(w.z, dz2[4 * q + 2], a2);
                    a3 = fmaf(w.w, dz2[4 * q + 3], a3);
                }
                float gh  = (a0 + a1) + (a2 + a3);
                float t   = h1[ii];
                float dz1 = gh * (1.0f - t * t);
                g0 = fmaf(s.W1[ii],       dz1, g0);
                g1 = fmaf(s.W1[64 + ii],  dz1, g1);
                g2 = fmaf(s.W1[128 + ii], dz1, g2);
            }

            // d feats / d d = [1, -1/d^2, -2/d^3], clip gate on dist<=0.05
            float gd = g0 - g1 * inv2 - 2.0f * g2 * inv2 * inv;
            gd = (dist > 0.05f) ? gd : 0.0f;
            // unordered pair: grad_i = +gd*r/dist, grad_j = -gd*r/dist; F = -grad
            float coef = gd * __fdividef(1.0f, dist);
            float cx = coef * rx, cy = coef * ry, cz = coef * rz;
            atomicAdd(&s.F[i * 3 + 0], -cx);
            atomicAdd(&s.F[i * 3 + 1], -cy);
            atomicAdd(&s.F[i * 3 + 2], -cz);
            atomicAdd(&s.F[j * 3 + 0],  cx);
            atomicAdd(&s.F[j * 3 + 1],  cy);
            atomicAdd(&s.F[j * 3 + 2],  cz);
        }

        atomicAdd(&s.Vsum, vloc);
        __syncthreads();

        for (int k = tid; k < NPART * 3; k += TPB)
            out[b * (NPART * 3) + k] = s.F[k];
        if (tid == 0)
            out[(long long)B * (NPART * 3) + b] = s.Vsum;
        __syncthreads();  // protect s.pos / s.F before next batch iteration
    }
}

extern "C" void kernel_launch(void* const* d_in, const int* in_sizes, int n_in,
                              void* d_out, int out_size)
{
    const float* pos = (const float*)d_in[0];
    const float* W1  = (const float*)d_in[1];
    const float* b1  = (const float*)d_in[2];
    const float* W2  = (const float*)d_in[3];
    const float* b2  = (const float*)d_in[4];
    const float* W3  = (const float*)d_in[5];
    const float* b3  = (const float*)d_in[6];
    float* out = (float*)d_out;
    const int B = in_sizes[0] / (NPART * 3);

    discovery_kernel<<<GRID, TPB>>>(pos, W1, b1, W2, b2, W3, b3, out, B);
}

// round 2
// speedup vs baseline: 1.7136x; 1.7136x over previous
#include <cuda_runtime.h>

#define NPART 32
#define NPAIR 496          // 32*31/2 unordered pairs
#define TPB   256
#define GRID  1024
#define RS    68           // W2T row stride in floats; odd half at +36 (bank-safe)

__device__ __forceinline__ float fast_tanh(float x) {
    float ax = fabsf(x);
    float e  = __expf(ax + ax);                     // MUFU-based
    float t  = 1.0f - __fdividef(2.0f, e + 1.0f);   // e=inf -> t=1
    return copysignf(t, x);
}

struct Smem {
    float W2T[64 * RS];   // row jj: [0..31]=k 0..31, [36..67]=k 32..63
    float W1[192];        // [c][k]
    float b1[64], b2[64], W3[64];
    float pos[NPART * 3];
    float F[NPART * 3];
    float Vsum;
    unsigned char pi[NPAIR], pj[NPAIR];
};

__global__ void __launch_bounds__(TPB, 2)
discovery_kernel(const float* __restrict__ gpos,
                 const float* __restrict__ gW1, const float* __restrict__ gb1,
                 const float* __restrict__ gW2, const float* __restrict__ gb2,
                 const float* __restrict__ gW3, const float* __restrict__ gb3,
                 float* __restrict__ out, int B)
{
    __shared__ Smem s;
    const int tid  = threadIdx.x;
    const int half = tid & 1;          // which 32-wide k-half this lane owns
    const int psl  = tid >> 1;         // pair slot 0..127
    const int kb   = half * 32;        // k base of my half

    // ---- weights into smem (once per block) ----
    for (int idx = tid; idx < 4096; idx += TPB) {
        int k = idx >> 6, jj = idx & 63;            // gW2 is [k][jj]
        int col = (k < 32) ? k : (k + 4);           // odd half shifted by +4 floats
        s.W2T[jj * RS + col] = gW2[idx];
    }
    for (int k = tid; k < 192; k += TPB) s.W1[k] = gW1[k];
    for (int k = tid; k < 64; k += TPB) {
        s.b1[k] = gb1[k]; s.b2[k] = gb2[k]; s.W3[k] = gW3[k];
    }
    const float b3v = gb3[0];

    // pair table in diagonal order: d=1..31, (i, i+d)
    for (int k = tid; k < NPAIR; k += TPB) {
        int d = 1, c = 0;
        while (k >= c + (NPART - d)) { c += NPART - d; d++; }
        int i = k - c;
        s.pi[k] = (unsigned char)i;
        s.pj[k] = (unsigned char)(i + d);
    }
    __syncthreads();

    for (int b = blockIdx.x; b < B; b += gridDim.x) {
        for (int k = tid; k < NPART * 3; k += TPB) {
            s.pos[k] = gpos[b * (NPART * 3) + k];
            s.F[k]   = 0.0f;
        }
        if (tid == 0) s.Vsum = 0.0f;
        __syncthreads();

        float vloc = 0.0f;   // per-batch V accumulator (even lanes only)

        for (int k = psl; k < NPAIR; k += TPB / 2) {
            const int i = s.pi[k], j = s.pj[k];
            const float rx = s.pos[i * 3 + 0] - s.pos[j * 3 + 0];
            const float ry = s.pos[i * 3 + 1] - s.pos[j * 3 + 1];
            const float rz = s.pos[i * 3 + 2] - s.pos[j * 3 + 2];
            const float dist = sqrtf(rx * rx + ry * ry + rz * rz);
            const float d    = fmaxf(dist, 0.05f);
            const float inv  = __fdividef(1.0f, d);
            const float inv2 = inv * inv;

            // layer 1 (my 32 of 64 hidden units)
            float h1[32];
            #pragma unroll 8
            for (int q = 0; q < 32; q++) {
                float z = s.b1[kb + q] + d * s.W1[kb + q]
                        + inv * s.W1[64 + kb + q] + inv2 * s.W1[128 + kb + q];
                h1[q] = fast_tanh(z);
            }

            float gh1[32];
            #pragma unroll
            for (int q = 0; q < 32; q++) gh1[q] = 0.0f;

            float v = b3v;
            const float4* wbase = (const float4*)(&s.W2T[half * 36]);

            // fused layer-2 forward + backward-through-W2
            #pragma unroll 4
            for (int jj = 0; jj < 64; jj++) {
                const float4* wr = wbase + jj * (RS / 4);
                float4 w[8];
                #pragma unroll
                for (int q = 0; q < 8; q++) w[q] = wr[q];

                float a0 = 0.f, a1 = 0.f, a2 = 0.f, a3 = 0.f;
                #pragma unroll
                for (int q = 0; q < 8; q++) {
                    a0 = fmaf(h1[4 * q + 0], w[q].x, a0);
                    a1 = fmaf(h1[4 * q + 1], w[q].y, a1);
                    a2 = fmaf(h1[4 * q + 2], w[q].z, a2);
                    a3 = fmaf(h1[4 * q + 3], w[q].w, a3);
                }
                float part  = (a0 + a1) + (a2 + a3);
                float other = __shfl_xor_sync(0xffffffffu, part, 1);
                float pe = half ? other : part;     // fixed order: both lanes
                float po = half ? part  : other;    // compute identical z
                float z  = s.b2[jj] + pe + po;
                float t  = fast_tanh(z);
                float w3 = s.W3[jj];
                v = fmaf(t, w3, v);
                float dz2 = w3 * (1.0f - t * t);
                #pragma unroll
                for (int q = 0; q < 8; q++) {
                    gh1[4 * q + 0] = fmaf(w[q].x, dz2, gh1[4 * q + 0]);
                    gh1[4 * q + 1] = fmaf(w[q].y, dz2, gh1[4 * q + 1]);
                    gh1[4 * q + 2] = fmaf(w[q].z, dz2, gh1[4 * q + 2]);
                    gh1[4 * q + 3] = fmaf(w[q].w, dz2, gh1[4 * q + 3]);
                }
            }

            // backward through layer 1 (my half), then combine halves
            float g0 = 0.f, g1 = 0.f, g2 = 0.f;
            #pragma unroll 8
            for (int q = 0; q < 32; q++) {
                float t   = h1[q];
                float dz1 = gh1[q] * (1.0f - t * t);
                g0 = fmaf(s.W1[kb + q],       dz1, g0);
                g1 = fmaf(s.W1[64 + kb + q],  dz1, g1);
                g2 = fmaf(s.W1[128 + kb + q], dz1, g2);
            }
            g0 += __shfl_xor_sync(0xffffffffu, g0, 1);
            g1 += __shfl_xor_sync(0xffffffffu, g1, 1);
            g2 += __shfl_xor_sync(0xffffffffu, g2, 1);

            if (!half) {
                float gd = g0 - g1 * inv2 - 2.0f * g2 * inv2 * inv;
                gd = (dist > 0.05f) ? gd : 0.0f;
                float coef = gd * __fdividef(1.0f, dist);
                float cx = coef * rx, cy = coef * ry, cz = coef * rz;
                atomicAdd(&s.F[i * 3 + 0], -cx);
                atomicAdd(&s.F[i * 3 + 1], -cy);
                atomicAdd(&s.F[i * 3 + 2], -cz);
                atomicAdd(&s.F[j * 3 + 0],  cx);
                atomicAdd(&s.F[j * 3 + 1],  cy);
                atomicAdd(&s.F[j * 3 + 2],  cz);
                vloc += v;
            }
        }

        // warp-reduce vloc (odd lanes carry 0), one atomic per warp
        #pragma unroll
        for (int off = 16; off; off >>= 1)
            vloc += __shfl_xor_sync(0xffffffffu, vloc, off);
        if ((tid & 31) == 0) atomicAdd(&s.Vsum, vloc);
        __syncthreads();

        for (int k = tid; k < NPART * 3; k += TPB)
            out[b * (NPART * 3) + k] = s.F[k];
        if (tid == 0)
            out[(long long)B * (NPART * 3) + b] = s.Vsum;
        __syncthreads();   // protect s.pos / s.F / s.Vsum before next batch
    }
}

extern "C" void kernel_launch(void* const* d_in, const int* in_sizes, int n_in,
                              void* d_out, int out_size)
{
    const float* pos = (const float*)d_in[0];
    const float* W1  = (const float*)d_in[1];
    const float* b1  = (const float*)d_in[2];
    const float* W2  = (const float*)d_in[3];
    const float* b2  = (const float*)d_in[4];
    const float* W3  = (const float*)d_in[5];
    const float* b3  = (const float*)d_in[6];
    float* out = (float*)d_out;
    const int B = in_sizes[0] / (NPART * 3);

    discovery_kernel<<<GRID, TPB>>>(pos, W1, b1, W2, b2, W3, b3, out, B);
}

// round 3
// speedup vs baseline: 41.4088x; 24.1645x over previous
#include <cuda_runtime.h>
#include <math.h>

#define NPART 32
#define NPAIR 496
#define NT    4096                 // table nodes
#define TPB_B 256
#define GRID_B 1024

// t = log(d) uniform over [log(0.05), log(32)]
#define T0F   (-2.99573227355399099343f)   // logf(0.05)
#define T1F   ( 3.46573590279972654709f)   // logf(32)
#define HTF   ((T1F - T0F) / (float)(NT - 1))
#define INVHT ((float)(NT - 1) / (T1F - T0F))

__device__ float2 g_table[NT];     // (v(d), dv/dt) at node i

// ---------------------------------------------------------------------------
// Kernel A: build table. One thread per node. Forward-mode AD w.r.t. d.
// ---------------------------------------------------------------------------
__global__ void __launch_bounds__(256)
build_table(const float* __restrict__ gW1, const float* __restrict__ gb1,
            const float* __restrict__ gW2, const float* __restrict__ gb2,
            const float* __restrict__ gW3, const float* __restrict__ gb3)
{
    __shared__ float sW2T[64 * 64];   // [jj][k]
    __shared__ float sW1[192], sb1[64], sb2[64], sW3[64];
    const int tid = threadIdx.x;

    for (int idx = tid; idx < 4096; idx += 256) {
        int k = idx >> 6, jj = idx & 63;          // gW2 is [k][jj]
        sW2T[jj * 64 + k] = gW2[idx];
    }
    for (int k = tid; k < 192; k += 256) sW1[k] = gW1[k];
    for (int k = tid; k < 64; k += 256) {
        sb1[k] = gb1[k]; sb2[k] = gb2[k]; sW3[k] = gW3[k];
    }
    __syncthreads();

    const int node = blockIdx.x * 256 + tid;
    if (node >= NT) return;

    const float t = T0F + node * HTF;
    const float d = expf(t);
    const float inv = 1.0f / d, inv2 = inv * inv;
    // feats and their d-derivatives
    const float f1 = d, f2 = inv, f3 = inv2;
    const float e1 = 1.0f, e2 = -inv2, e3 = -2.0f * inv2 * inv;

    float h[64], th[64];
    #pragma unroll 8
    for (int k = 0; k < 64; k++) {
        float w0 = sW1[k], w1 = sW1[64 + k], w2 = sW1[128 + k];
        float z  = sb1[k] + f1 * w0 + f2 * w1 + f3 * w2;
        float hk = tanhf(z);
        h[k]  = hk;
        th[k] = (1.0f - hk * hk) * (e1 * w0 + e2 * w1 + e3 * w2);
    }

    float v = gb3[0], gd = 0.0f;
    #pragma unroll 2
    for (int jj = 0; jj < 64; jj++) {
        const float4* row = (const float4*)(&sW2T[jj * 64]);
        float a0 = 0.f, a1 = 0.f, b0 = 0.f, b1 = 0.f;
        #pragma unroll
        for (int q = 0; q < 16; q++) {
            float4 w = row[q];
            a0 = fmaf(h[4 * q + 0],  w.x, a0);
            a1 = fmaf(h[4 * q + 1],  w.y, a1);
            a0 = fmaf(h[4 * q + 2],  w.z, a0);
            a1 = fmaf(h[4 * q + 3],  w.w, a1);
            b0 = fmaf(th[4 * q + 0], w.x, b0);
            b1 = fmaf(th[4 * q + 1], w.y, b1);
            b0 = fmaf(th[4 * q + 2], w.z, b0);
            b1 = fmaf(th[4 * q + 3], w.w, b1);
        }
        float z2 = sb2[jj] + a0 + a1;
        float tz = b0 + b1;                       // dz2/dd
        float t2 = tanhf(z2);
        float w3 = sW3[jj];
        v  = fmaf(t2, w3, v);
        gd = fmaf(w3 * (1.0f - t2 * t2), tz, gd); // dv/dd
    }
    g_table[node] = make_float2(v, gd * d);       // store dv/dt = dv/dd * d
}

// ---------------------------------------------------------------------------
// Kernel B: per-batch pair loop with Hermite table lookup.
// ---------------------------------------------------------------------------
__global__ void __launch_bounds__(TPB_B)
forces_kernel(const float* __restrict__ gpos, float* __restrict__ out, int B)
{
    __shared__ float pos[NPART * 3];
    __shared__ float F[NPART * 3];
    __shared__ float Vsum;
    __shared__ unsigned char pi[NPAIR], pj[NPAIR];
    const int tid = threadIdx.x;

    // pair table: diagonal order d=1..31, (i, i+d)
    for (int k = tid; k < NPAIR; k += TPB_B) {
        int dd = 1, c = 0;
        while (k >= c + (NPART - dd)) { c += NPART - dd; dd++; }
        int i = k - c;
        pi[k] = (unsigned char)i;
        pj[k] = (unsigned char)(i + dd);
    }
    __syncthreads();

    for (int b = blockIdx.x; b < B; b += gridDim.x) {
        for (int k = tid; k < NPART * 3; k += TPB_B) {
            pos[k] = gpos[b * (NPART * 3) + k];
            F[k]   = 0.0f;
        }
        if (tid == 0) Vsum = 0.0f;
        __syncthreads();

        float vloc = 0.0f;

        for (int k = tid; k < NPAIR; k += TPB_B) {
            const int i = pi[k], j = pj[k];
            const float rx = pos[i * 3 + 0] - pos[j * 3 + 0];
            const float ry = pos[i * 3 + 1] - pos[j * 3 + 1];
            const float rz = pos[i * 3 + 2] - pos[j * 3 + 2];
            const float dist = sqrtf(rx * rx + ry * ry + rz * rz);

            if (dist > 0.05f) {
                float t = logf(dist);
                float u = (t - T0F) * INVHT;
                u = fminf(fmaxf(u, 0.0f), (float)NT - 1.001f);
                int   i0 = (int)u;
                float s  = u - (float)i0;
                float2 e0 = g_table[i0];
                float2 e1 = g_table[i0 + 1];

                float s2 = s * s, s3 = s2 * s;
                float h00 = 2.f * s3 - 3.f * s2 + 1.f;
                float h10 = s3 - 2.f * s2 + s;
                float h01 = 3.f * s2 - 2.f * s3;
                float h11 = s3 - s2;
                float v = e0.x * h00 + e1.x * h01
                        + (e0.y * h10 + e1.y * h11) * HTF;

                float d00 = 6.f * (s2 - s);                // dh00/ds
                float d10 = 3.f * s2 - 4.f * s + 1.f;
                float d11 = 3.f * s2 - 2.f * s;
                float dpds = (e0.x - e1.x) * d00 + (e0.y * d10 + e1.y * d11) * HTF;
                // dv/dt = dpds/HT ; dv/dd = dv/dt / d ; coef = (dv/dd)/dist
                float coef = dpds * INVHT / (dist * dist);

                float cx = coef * rx, cy = coef * ry, cz = coef * rz;
                atomicAdd(&F[i * 3 + 0], -cx);
                atomicAdd(&F[i * 3 + 1], -cy);
                atomicAdd(&F[i * 3 + 2], -cz);
                atomicAdd(&F[j * 3 + 0],  cx);
                atomicAdd(&F[j * 3 + 1],  cy);
                atomicAdd(&F[j * 3 + 2],  cz);
                vloc += v;
            } else {
                vloc += g_table[0].x;    // clipped: constant v, zero force
            }
        }

        #pragma unroll
        for (int off = 16; off; off >>= 1)
            vloc += __shfl_xor_sync(0xffffffffu, vloc, off);
        if ((tid & 31) == 0) atomicAdd(&Vsum, vloc);
        __syncthreads();

        for (int k = tid; k < NPART * 3; k += TPB_B)
            out[b * (NPART * 3) + k] = F[k];
        if (tid == 0)
            out[(long long)B * (NPART * 3) + b] = Vsum;
        __syncthreads();
    }
}

extern "C" void kernel_launch(void* const* d_in, const int* in_sizes, int n_in,
                              void* d_out, int out_size)
{
    const float* pos = (const float*)d_in[0];
    const float* W1  = (const float*)d_in[1];
    const float* b1  = (const float*)d_in[2];
    const float* W2  = (const float*)d_in[3];
    const float* b2  = (const float*)d_in[4];
    const float* W3  = (const float*)d_in[5];
    const float* b3  = (const float*)d_in[6];
    float* out = (float*)d_out;
    const int B = in_sizes[0] / (NPART * 3);

    build_table<<<NT / 256, 256>>>(W1, b1, W2, b2, W3, b3);
    forces_kernel<<<GRID_B, TPB_B>>>(pos, out, B);
}